// round 8
// baseline (speedup 1.0000x reference)
#include <cuda_runtime.h>
#include <cuda_bf16.h>
#include <math.h>

#define NODES   100000
#define EDGES   400000
#define EMB     300
#define HID     600
#define NGRAPH  4096
#define NLAYERS 5
#define CH4     75          // EMB/4
#define BN_EPS  1e-5f
#define INV_TEMP 25.0f      // 1/0.04

// padded dims: K multiple of 16, N multiple of 64
#define KP1   304           // K of GEMM1/proj (EMB=300)
#define KP2   608           // K of GEMM2 (HID=600)
#define NP1   640           // N of GEMM1 (HID=600)
#define NP2   320           // N of GEMM2/proj (EMB=300)

// ------------------------- scratch (device globals; no allocation) ----------
__device__ float g_h   [NODES * EMB];
__device__ float g_agg [NODES * EMB];
__device__ float g_f0  [NGRAPH * EMB];
__device__ float g_f1  [NGRAPH * EMB];
__device__ float g_pool[NGRAPH * EMB];
__device__ float g_cnt [NGRAPH];
__device__ float g_sum [EMB];
__device__ float g_sqs [EMB];
// bf16-split activations (padded, zero-init pads never written)
__device__ uint4 g_s_hi  [NODES * (KP1 / 8)];     // [NODES][304] bf16
__device__ uint4 g_s_lo  [NODES * (KP1 / 8)];
__device__ uint4 g_hid_hi[NODES * (KP2 / 8)];     // [NODES][608] bf16
__device__ uint4 g_hid_lo[NODES * (KP2 / 8)];
// pre-transposed weight images [Np][Kp] bf16 hi/lo
#define W1IMG (NP1 * KP1)
#define W2IMG (NP2 * KP2)
#define WPIMG (NP2 * KP1)
__device__ unsigned short g_w1i_h[NLAYERS * W1IMG];
__device__ unsigned short g_w1i_l[NLAYERS * W1IMG];
__device__ unsigned short g_w2i_h[NLAYERS * W2IMG];
__device__ unsigned short g_w2i_l[NLAYERS * W2IMG];
__device__ unsigned short g_wpi_h[WPIMG];
__device__ unsigned short g_wpi_l[WPIMG];

// ------------------------- helpers ------------------------------------------
__device__ __forceinline__ void red4(float* p, float x, float y, float z, float w) {
    unsigned long long gp = __cvta_generic_to_global(p);
    asm volatile("red.global.add.v4.f32 [%0], {%1,%2,%3,%4};"
                 :: "l"(gp), "f"(x), "f"(y), "f"(z), "f"(w) : "memory");
}
__device__ __forceinline__ unsigned pack_bf16(float lo, float hi) {
    unsigned r;
    asm("cvt.rn.bf16x2.f32 %0, %1, %2;" : "=r"(r) : "f"(hi), "f"(lo));
    return r;
}
__device__ __forceinline__ float bf_lo(unsigned w) { return __uint_as_float(w << 16); }
__device__ __forceinline__ float bf_hi(unsigned w) { return __uint_as_float(w & 0xffff0000u); }

__device__ __forceinline__ unsigned smem_u32(const void* p) {
    unsigned a;
    asm("{ .reg .u64 t; cvta.to.shared.u64 t, %1; cvt.u32.u64 %0, t; }"
        : "=r"(a) : "l"(p));
    return a;
}
__device__ __forceinline__ void mma_bf16(float* c, const unsigned* a, const unsigned* b) {
    asm volatile(
        "mma.sync.aligned.m16n8k16.row.col.f32.bf16.bf16.f32 "
        "{%0,%1,%2,%3},{%4,%5,%6,%7},{%8,%9},{%0,%1,%2,%3};"
        : "+f"(c[0]), "+f"(c[1]), "+f"(c[2]), "+f"(c[3])
        : "r"(a[0]), "r"(a[1]), "r"(a[2]), "r"(a[3]), "r"(b[0]), "r"(b[1]));
}
__device__ __forceinline__ void ldmx4(unsigned* r, unsigned addr) {
    asm volatile("ldmatrix.sync.aligned.m8n8.x4.shared.b16 {%0,%1,%2,%3}, [%4];"
        : "=r"(r[0]), "=r"(r[1]), "=r"(r[2]), "=r"(r[3]) : "r"(addr));
}

// ------------------------- weight image prep ---------------------------------
// out: [Np][Kp] bf16 hi/lo, value = w[k*N+n], zero-padded
__global__ void k_prep(const float* __restrict__ w, int K, int N, int Kp, int Np,
                       unsigned short* __restrict__ ih,
                       unsigned short* __restrict__ il) {
    int idx = blockIdx.x * blockDim.x + threadIdx.x;
    if (idx >= Np * Kp) return;
    int n = idx / Kp, k = idx % Kp;
    float v = (n < N && k < K) ? w[(size_t)k * N + n] : 0.f;
    unsigned h = pack_bf16(v, 0.f);
    unsigned l = pack_bf16(v - bf_lo(h), 0.f);
    ih[idx] = (unsigned short)(h & 0xffff);
    il[idx] = (unsigned short)(l & 0xffff);
}

// split fp32 [NODES][K] -> padded bf16 hi/lo u32 [NODES][halfKp]
__global__ void k_split(const float* __restrict__ src, int K,
                        unsigned* __restrict__ hi, unsigned* __restrict__ lo,
                        int halfKp) {
    int idx = blockIdx.x * blockDim.x + threadIdx.x;
    if (idx >= NODES * halfKp) return;
    int node = idx / halfKp, p = idx % halfKp;
    int k = 2 * p;
    float v0 = (k < K) ? src[(size_t)node * K + k] : 0.f;
    float v1 = (k + 1 < K) ? src[(size_t)node * K + k + 1] : 0.f;
    unsigned h = pack_bf16(v0, v1);
    hi[idx] = h;
    lo[idx] = pack_bf16(v0 - bf_lo(h), v1 - bf_hi(h));
}

// ------------------------- mma.sync GEMM with ldmatrix -----------------------
// C[M,N] = A @ Bw + bias, 3-term bf16 split. CTA tile 128x64, BK=16, 8 warps
// (warp 32x32). smem rows k-contiguous, 48B stride (conflict-free ldmatrix).
#define RSTR 12                     // u32 per smem row (48B: 32 data + 16 pad)
#define A_SZ (128 * RSTR)           // u32
#define B_SZ (64 * RSTR)
#define STGU (2 * A_SZ + 2 * B_SZ)  // u32 per stage
#define AhO  0
#define AlO  A_SZ
#define BhO  (2 * A_SZ)
#define BlO  (2 * A_SZ + B_SZ)

__global__ __launch_bounds__(256)
void k_gemm8(const uint4* __restrict__ Ahi, const uint4* __restrict__ Alo,
             const uint4* __restrict__ Bhi, const uint4* __restrict__ Blo,
             const float* __restrict__ bias,
             float* __restrict__ Cf,
             unsigned* __restrict__ Ohi, unsigned* __restrict__ Olo, int halfKpO,
             int M, int N, int Kp, int relu) {
    __shared__ __align__(16) unsigned sm[2 * STGU];

    int tid = threadIdx.x, lane = tid & 31, warp = tid >> 5;
    int wm = warp >> 1;             // 0..3  -> m offset wm*32
    int wn = warp & 1;              // 0..1  -> n offset wn*32
    int g = lane >> 2, t = lane & 3;
    int rowBase = blockIdx.y * 128;
    int colBase = blockIdx.x * 64;
    int rowU4 = Kp >> 3;            // uint4 per activation row
    int KCn = Kp >> 4;              // k16 chunks

    // loader mapping
    int arow = tid >> 1, aseg = tid & 1;          // A: 128 rows x 2 segs
    int bpart = tid >> 7;                          // 0=hi, 1=lo
    int brow = (tid >> 1) & 63, bseg = tid & 1;    // B: 64 rows x 2 segs

    // ldmatrix lane offset within a tile (bytes)
    unsigned smb = smem_u32(sm);
    unsigned lmo = (lane & 15) * 48u + (lane >> 4) * 16u;
    unsigned aF = (wm * 32) * 48u + lmo;           // + i*768 per m16 frag
    unsigned bF = (wn * 32) * 48u + lmo;           // + j2*768 per n16 group

    float acc[2][4][4] = {};
    uint4 pah, pal, pbv;

    // ---- prefetch chunk 0 ----
    {
        int gr = rowBase + arow;
        pah = make_uint4(0, 0, 0, 0); pal = make_uint4(0, 0, 0, 0);
        if (gr < M) {
            size_t s = (size_t)gr * rowU4 + aseg;
            pah = Ahi[s]; pal = Alo[s];
        }
        size_t bs = (size_t)(colBase + brow) * (Kp >> 3) + bseg;
        pbv = bpart ? Blo[bs] : Bhi[bs];
    }
    int buf = 0;
    {
        unsigned ao = arow * RSTR + aseg * 4;
        *(uint4*)&sm[AhO + ao] = pah;
        *(uint4*)&sm[AlO + ao] = pal;
        *(uint4*)&sm[(bpart ? BlO : BhO) + brow * RSTR + bseg * 4] = pbv;
    }
    __syncthreads();

    for (int kc = 0; kc < KCn; kc++) {
        if (kc + 1 < KCn) {
            int gr = rowBase + arow;
            pah = make_uint4(0, 0, 0, 0); pal = make_uint4(0, 0, 0, 0);
            if (gr < M) {
                size_t s = (size_t)gr * rowU4 + (kc + 1) * 2 + aseg;
                pah = Ahi[s]; pal = Alo[s];
            }
            size_t bs = (size_t)(colBase + brow) * (Kp >> 3) + (kc + 1) * 2 + bseg;
            pbv = bpart ? Blo[bs] : Bhi[bs];
        }
        // ---- compute chunk on buf ----
        {
            unsigned sb = smb + buf * (STGU * 4);
            unsigned Afh[2][4], Afl[2][4];
#pragma unroll
            for (int i = 0; i < 2; i++) {
                ldmx4(Afh[i], sb + AhO * 4 + aF + i * 768u);
                ldmx4(Afl[i], sb + AlO * 4 + aF + i * 768u);
            }
            unsigned Bfh[4][2], Bfl[4][2];
#pragma unroll
            for (int j2 = 0; j2 < 2; j2++) {
                unsigned r[4];
                ldmx4(r, sb + BhO * 4 + bF + j2 * 768u);
                Bfh[2 * j2][0] = r[0]; Bfh[2 * j2 + 1][0] = r[1];
                Bfh[2 * j2][1] = r[2]; Bfh[2 * j2 + 1][1] = r[3];
                ldmx4(r, sb + BlO * 4 + bF + j2 * 768u);
                Bfl[2 * j2][0] = r[0]; Bfl[2 * j2 + 1][0] = r[1];
                Bfl[2 * j2][1] = r[2]; Bfl[2 * j2 + 1][1] = r[3];
            }
#pragma unroll
            for (int i = 0; i < 2; i++)
#pragma unroll
                for (int j = 0; j < 4; j++) {
                    mma_bf16(acc[i][j], Afl[i], Bfh[j]);   // lo*hi
                    mma_bf16(acc[i][j], Afh[i], Bfl[j]);   // hi*lo
                    mma_bf16(acc[i][j], Afh[i], Bfh[j]);   // hi*hi
                }
        }
        if (kc + 1 < KCn) {
            buf ^= 1;
            __syncthreads();
            unsigned* st = sm + buf * STGU;
            unsigned ao = arow * RSTR + aseg * 4;
            *(uint4*)&st[AhO + ao] = pah;
            *(uint4*)&st[AlO + ao] = pal;
            *(uint4*)&st[(bpart ? BlO : BhO) + brow * RSTR + bseg * 4] = pbv;
            __syncthreads();
        }
    }

    // ---- epilogue ----
#pragma unroll
    for (int i = 0; i < 2; i++) {
#pragma unroll
        for (int j = 0; j < 4; j++) {
            int gc = colBase + wn * 32 + j * 8 + t * 2;
            if (gc >= N) continue;
            float b0 = bias[gc], b1 = bias[gc + 1];
            int gr0 = rowBase + wm * 32 + i * 16 + g;
            int gr1 = gr0 + 8;
            float o0 = acc[i][j][0] + b0, o1 = acc[i][j][1] + b1;
            float o2 = acc[i][j][2] + b0, o3 = acc[i][j][3] + b1;
            if (relu) {
                o0 = fmaxf(o0, 0.f); o1 = fmaxf(o1, 0.f);
                o2 = fmaxf(o2, 0.f); o3 = fmaxf(o3, 0.f);
            }
            if (Cf) {
                if (gr0 < M) *(float2*)(Cf + (size_t)gr0 * N + gc) = make_float2(o0, o1);
                if (gr1 < M) *(float2*)(Cf + (size_t)gr1 * N + gc) = make_float2(o2, o3);
            } else {
                int cp = gc >> 1;
                if (gr0 < M) {
                    unsigned h = pack_bf16(o0, o1);
                    Ohi[(size_t)gr0 * halfKpO + cp] = h;
                    Olo[(size_t)gr0 * halfKpO + cp] =
                        pack_bf16(o0 - bf_lo(h), o1 - bf_hi(h));
                }
                if (gr1 < M) {
                    unsigned h = pack_bf16(o2, o3);
                    Ohi[(size_t)gr1 * halfKpO + cp] = h;
                    Olo[(size_t)gr1 * halfKpO + cp] =
                        pack_bf16(o2 - bf_lo(h), o3 - bf_hi(h));
                }
            }
        }
    }
}

// ------------------------- h init: h = ae1[x0]+ae2[x1]; agg = h + self0 -----
__global__ void k_init_h(const int* __restrict__ x,
                         const float* __restrict__ ae1,
                         const float* __restrict__ ae2,
                         const float* __restrict__ s1,
                         const float* __restrict__ s2) {
    int idx = blockIdx.x * blockDim.x + threadIdx.x;
    if (idx >= NODES * CH4) return;
    int node = idx / CH4, c = idx % CH4;
    int i0 = x[2 * node], i1 = x[2 * node + 1];
    float4 a = ((const float4*)ae1)[i0 * CH4 + c];
    float4 b = ((const float4*)ae2)[i1 * CH4 + c];
    float4 h = make_float4(a.x + b.x, a.y + b.y, a.z + b.z, a.w + b.w);
    ((float4*)g_h)[idx] = h;
    float4 v1 = ((const float4*)s1)[c];
    float4 v2 = ((const float4*)s2)[c];
    ((float4*)g_agg)[idx] = make_float4(h.x + v1.x + v2.x, h.y + v1.y + v2.y,
                                        h.z + v1.z + v2.z, h.w + v1.w + v2.w);
}

// ------------------------- edge scatter: agg[dst] += h[src] + eemb ----------
__global__ void k_edge_scatter(const int* __restrict__ ei,
                               const int* __restrict__ ea,
                               const float* __restrict__ ee1,
                               const float* __restrict__ ee2, int layer) {
    __shared__ __align__(16) float se1[6 * EMB];
    __shared__ __align__(16) float se2[3 * EMB];
    const float* t1 = ee1 + layer * 6 * EMB;
    const float* t2 = ee2 + layer * 3 * EMB;
    for (int i = threadIdx.x; i < 6 * EMB; i += blockDim.x) se1[i] = t1[i];
    for (int i = threadIdx.x; i < 3 * EMB; i += blockDim.x) se2[i] = t2[i];
    __syncthreads();

    int lane  = threadIdx.x & 31;
    int warp  = (blockIdx.x * blockDim.x + threadIdx.x) >> 5;
    int nwarp = (gridDim.x * blockDim.x) >> 5;
    const float4* h4  = (const float4*)g_h;
    const float4* s14 = (const float4*)se1;
    const float4* s24 = (const float4*)se2;

    for (int e = warp; e < EDGES; e += nwarp) {
        int src = ei[e];
        int dst = ei[EDGES + e];
        int a0  = ea[2 * e];
        int a1  = ea[2 * e + 1];
        const float4* hs = h4 + (size_t)src * CH4;
        const float4* p1 = s14 + a0 * CH4;
        const float4* p2 = s24 + a1 * CH4;
        float* ad = g_agg + (size_t)dst * EMB;
        for (int c = lane; c < CH4; c += 32) {
            float4 hv = hs[c], v1 = p1[c], v2 = p2[c];
            red4(ad + 4 * c, hv.x + v1.x + v2.x, hv.y + v1.y + v2.y,
                             hv.z + v1.z + v2.z, hv.w + v1.w + v2.w);
        }
    }
}

// ------------------------- batchnorm ---------------------------------------
__global__ void k_zero600() {
    int t = threadIdx.x;
    if (t < EMB) { g_sum[t] = 0.f; g_sqs[t] = 0.f; }
}

__global__ void k_bn_reduce() {
    int c = threadIdx.x;
    if (c >= EMB) return;
    int base = blockIdx.x * 256;
    float s = 0.f, q = 0.f;
    for (int r = 0; r < 256; r++) {
        int row = base + r;
        if (row < NODES) {
            float v = g_h[(size_t)row * EMB + c];
            s += v; q += v * v;
        }
    }
    atomicAdd(&g_sum[c], s);
    atomicAdd(&g_sqs[c], q);
}

__global__ void k_bn_norm(const float* __restrict__ gamma,
                          const float* __restrict__ beta,
                          const float* __restrict__ s1,
                          const float* __restrict__ s2, int doRelu) {
    int idx = blockIdx.x * blockDim.x + threadIdx.x;
    if (idx >= NODES * CH4) return;
    int c = idx % CH4;
    const float invN = 1.f / (float)NODES;
    float4 v  = ((const float4*)g_h)[idx];
    float4 s  = ((const float4*)g_sum)[c];
    float4 q  = ((const float4*)g_sqs)[c];
    float4 gm = ((const float4*)gamma)[c];
    float4 bt = ((const float4*)beta)[c];
    float m, var, is;
    m = s.x * invN; var = q.x * invN - m * m; is = rsqrtf(var + BN_EPS);
    v.x = (v.x - m) * is * gm.x + bt.x;
    m = s.y * invN; var = q.y * invN - m * m; is = rsqrtf(var + BN_EPS);
    v.y = (v.y - m) * is * gm.y + bt.y;
    m = s.z * invN; var = q.z * invN - m * m; is = rsqrtf(var + BN_EPS);
    v.z = (v.z - m) * is * gm.z + bt.z;
    m = s.w * invN; var = q.w * invN - m * m; is = rsqrtf(var + BN_EPS);
    v.w = (v.w - m) * is * gm.w + bt.w;
    if (doRelu) {
        v.x = fmaxf(v.x, 0.f); v.y = fmaxf(v.y, 0.f);
        v.z = fmaxf(v.z, 0.f); v.w = fmaxf(v.w, 0.f);
    }
    ((float4*)g_h)[idx] = v;
    if (s1) {
        float4 v1 = ((const float4*)s1)[c];
        float4 v2 = ((const float4*)s2)[c];
        ((float4*)g_agg)[idx] = make_float4(v.x + v1.x + v2.x, v.y + v1.y + v2.y,
                                            v.z + v1.z + v2.z, v.w + v1.w + v2.w);
    }
}

// ------------------------- pooling + normalize ------------------------------
__global__ void k_zero_pool() {
    int idx = blockIdx.x * blockDim.x + threadIdx.x;
    if (idx < NGRAPH * EMB) g_pool[idx] = 0.f;
    if (idx < NGRAPH) g_cnt[idx] = 0.f;
}

__global__ void k_pool_scatter(const int* __restrict__ batch) {
    int idx = blockIdx.x * blockDim.x + threadIdx.x;
    if (idx >= NODES * CH4) return;
    int node = idx / CH4, c = idx % CH4;
    int b = batch[node];
    float4 v = ((const float4*)g_agg)[idx];
    red4(g_pool + (size_t)b * EMB + 4 * c, v.x, v.y, v.z, v.w);
}

__global__ void k_count(const int* __restrict__ batch) {
    int i = blockIdx.x * blockDim.x + threadIdx.x;
    if (i < NODES) atomicAdd(&g_cnt[batch[i]], 1.f);
}

__global__ void k_finalize(int br) {
    int warp = (blockIdx.x * blockDim.x + threadIdx.x) >> 5;
    int lane = threadIdx.x & 31;
    if (warp >= NGRAPH) return;
    float* fout = br ? g_f1 : g_f0;
    float ic = 1.f / fmaxf(g_cnt[warp], 1.f);
    float sq = 0.f;
    for (int c = lane; c < EMB; c += 32) {
        float v = g_pool[(size_t)warp * EMB + c] * ic;
        sq += v * v;
    }
#pragma unroll
    for (int o = 16; o > 0; o >>= 1) sq += __shfl_xor_sync(0xffffffffu, sq, o);
    float rn = 1.f / fmaxf(sqrtf(sq), 1e-12f);
    for (int c = lane; c < EMB; c += 32)
        fout[(size_t)warp * EMB + c] = g_pool[(size_t)warp * EMB + c] * ic * rn;
}

// ------------------------- logits: out = (f0 @ f1^T) * 25 (exact fp32) ------
__global__ void k_logits(float* __restrict__ out) {
    __shared__ __align__(16) float As[16][64];
    __shared__ __align__(16) float Bs[16][64];
    int tx = threadIdx.x, ty = threadIdx.y;
    int tid = ty * 16 + tx;
    int rowBase = blockIdx.y * 64;
    int colBase = blockIdx.x * 64;
    float acc[4][4] = {};
    for (int kt = 0; kt < (EMB + 15) / 16; kt++) {
        int k0 = kt * 16;
        int c = tid & 15, r0 = tid >> 4;
#pragma unroll
        for (int p = 0; p < 4; p++) {
            int r = r0 + p * 16;
            int gc = k0 + c;
            As[c][r] = (gc < EMB) ? g_f0[(size_t)(rowBase + r) * EMB + gc] : 0.f;
            Bs[c][r] = (gc < EMB) ? g_f1[(size_t)(colBase + r) * EMB + gc] : 0.f;
        }
        __syncthreads();
#pragma unroll
        for (int kk = 0; kk < 16; kk++) {
            float4 a = *(const float4*)&As[kk][ty * 4];
            float4 b = *(const float4*)&Bs[kk][tx * 4];
            float ar[4] = {a.x, a.y, a.z, a.w};
            float br[4] = {b.x, b.y, b.z, b.w};
#pragma unroll
            for (int i = 0; i < 4; i++)
#pragma unroll
                for (int j = 0; j < 4; j++) acc[i][j] += ar[i] * br[j];
        }
        __syncthreads();
    }
#pragma unroll
    for (int i = 0; i < 4; i++)
#pragma unroll
        for (int j = 0; j < 4; j++)
            out[(size_t)(rowBase + ty * 4 + i) * NGRAPH + colBase + tx * 4 + j] =
                acc[i][j] * INV_TEMP;
}

// ------------------------- driver -------------------------------------------
extern "C" void kernel_launch(void* const* d_in, const int* in_sizes, int n_in,
                              void* d_out, int out_size) {
    (void)in_sizes; (void)n_in; (void)out_size;
    const int*   x[2]  = {(const int*)d_in[0], (const int*)d_in[4]};
    const int*   ei[2] = {(const int*)d_in[1], (const int*)d_in[5]};
    const int*   ea[2] = {(const int*)d_in[2], (const int*)d_in[6]};
    const int*   bt[2] = {(const int*)d_in[3], (const int*)d_in[7]};
    const float* ae1   = (const float*)d_in[8];
    const float* ae2   = (const float*)d_in[9];
    const float* ee1   = (const float*)d_in[10];
    const float* ee2   = (const float*)d_in[11];
    const float* w1    = (const float*)d_in[12];
    const float* b1    = (const float*)d_in[13];
    const float* w2    = (const float*)d_in[14];
    const float* b2    = (const float*)d_in[15];
    const float* gamma = (const float*)d_in[16];
    const float* beta  = (const float*)d_in[17];
    const float* pw    = (const float*)d_in[18];
    const float* pb    = (const float*)d_in[19];
    float* out = (float*)d_out;

    float *d_h, *d_agg;
    uint4 *d_shi, *d_slo, *d_hhi, *d_hlo;
    unsigned short *d_w1h, *d_w1l, *d_w2h, *d_w2l, *d_wph, *d_wpl;
    cudaGetSymbolAddress((void**)&d_h,   g_h);
    cudaGetSymbolAddress((void**)&d_agg, g_agg);
    cudaGetSymbolAddress((void**)&d_shi, g_s_hi);
    cudaGetSymbolAddress((void**)&d_slo, g_s_lo);
    cudaGetSymbolAddress((void**)&d_hhi, g_hid_hi);
    cudaGetSymbolAddress((void**)&d_hlo, g_hid_lo);
    cudaGetSymbolAddress((void**)&d_w1h, g_w1i_h);
    cudaGetSymbolAddress((void**)&d_w1l, g_w1i_l);
    cudaGetSymbolAddress((void**)&d_w2h, g_w2i_h);
    cudaGetSymbolAddress((void**)&d_w2l, g_w2i_l);
    cudaGetSymbolAddress((void**)&d_wph, g_wpi_h);
    cudaGetSymbolAddress((void**)&d_wpl, g_wpi_l);

    // ---- weight images ----
    for (int l = 0; l < NLAYERS; l++) {
        k_prep<<<(NP1 * KP1 + 255) / 256, 256>>>(
            w1 + (size_t)l * EMB * HID, EMB, HID, KP1, NP1,
            d_w1h + (size_t)l * W1IMG, d_w1l + (size_t)l * W1IMG);
        k_prep<<<(NP2 * KP2 + 255) / 256, 256>>>(
            w2 + (size_t)l * HID * EMB, HID, EMB, KP2, NP2,
            d_w2h + (size_t)l * W2IMG, d_w2l + (size_t)l * W2IMG);
    }
    k_prep<<<(NP2 * KP1 + 255) / 256, 256>>>(pw, EMB, EMB, KP1, NP2, d_wph, d_wpl);

    const int NCH = NODES * CH4;
    const int MT = (NODES + 127) / 128;      // 782
    dim3 grid1(NP1 / 64, MT);                // (10, 782)
    dim3 grid2(NP2 / 64, MT);                // (5, 782)

    const float* selfs1[NLAYERS];
    const float* selfs2[NLAYERS];
    for (int l = 0; l < NLAYERS; l++) {
        selfs1[l] = ee1 + (size_t)(l * 6 + 4) * EMB;
        selfs2[l] = ee2 + (size_t)(l * 3 + 0) * EMB;
    }

    for (int br = 0; br < 2; br++) {
        k_init_h<<<(NCH + 255) / 256, 256>>>(x[br], ae1, ae2, selfs1[0], selfs2[0]);
        for (int l = 0; l < NLAYERS; l++) {
            k_edge_scatter<<<2048, 256>>>(ei[br], ea[br], ee1, ee2, l);
            k_split<<<(NODES * (KP1 / 2) + 255) / 256, 256>>>(
                d_agg, EMB, (unsigned*)d_shi, (unsigned*)d_slo, KP1 / 2);
            // GEMM1: hid = relu(agg @ w1 + b1), split bf16 out
            k_gemm8<<<grid1, 256>>>(
                d_shi, d_slo,
                (const uint4*)(d_w1h + (size_t)l * W1IMG),
                (const uint4*)(d_w1l + (size_t)l * W1IMG),
                b1 + (size_t)l * HID, nullptr,
                (unsigned*)d_hhi, (unsigned*)d_hlo, KP2 / 2,
                NODES, HID, KP1, 1);
            // GEMM2: h = hid @ w2 + b2, f32 out
            k_gemm8<<<grid2, 256>>>(
                d_hhi, d_hlo,
                (const uint4*)(d_w2h + (size_t)l * W2IMG),
                (const uint4*)(d_w2l + (size_t)l * W2IMG),
                b2 + (size_t)l * EMB, d_h,
                nullptr, nullptr, 0,
                NODES, EMB, KP2, 0);
            k_zero600<<<1, 640>>>();
            k_bn_reduce<<<(NODES + 255) / 256, 320>>>();
            int last = (l == NLAYERS - 1);
            k_bn_norm<<<(NCH + 255) / 256, 256>>>(
                gamma + (size_t)l * EMB, beta + (size_t)l * EMB,
                last ? nullptr : selfs1[l + 1], last ? nullptr : selfs2[l + 1],
                !last);
        }
        // projector: p = h @ pw + pb (f32 into g_agg)
        k_split<<<(NODES * (KP1 / 2) + 255) / 256, 256>>>(
            d_h, EMB, (unsigned*)d_shi, (unsigned*)d_slo, KP1 / 2);
        k_gemm8<<<grid2, 256>>>(
            d_shi, d_slo, (const uint4*)d_wph, (const uint4*)d_wpl,
            pb, d_agg, nullptr, nullptr, 0,
            NODES, EMB, KP1, 0);
        k_zero_pool<<<(NGRAPH * EMB + 255) / 256, 256>>>();
        k_pool_scatter<<<(NCH + 255) / 256, 256>>>(bt[br]);
        k_count<<<(NODES + 255) / 256, 256>>>(bt[br]);
        k_finalize<<<(NGRAPH * 32 + 255) / 256, 256>>>(br);
    }
    k_logits<<<dim3(NGRAPH / 64, NGRAPH / 64), dim3(16, 16)>>>(out);
}